// round 14
// baseline (speedup 1.0000x reference)
#include <cuda_runtime.h>
#include <cuda_bf16.h>
#include <cstdint>

// Problem shape (fixed by the dataset)
#define B_  32
#define T_  768
#define C_  448
#define E_  256
#define N_  3136          // H*W = 56*56
#define SCALE 0.0625f     // 1/sqrt(E)

#define CHUNK 16
#define GX 196                // pixel-groups per batch: 196*16 = 3136 exact

#define QA_BLOCKS (32 * B_)   // 1024 qa blocks
#define M_BLOCKS  64          // each computes 7 rows of M
#define CPM 7                 // 64*7 = 448 exact

// -------- device scratch (no allocations allowed) --------
// g_a/g_qkb zeroed in residual tail; g_S/g_D zeroed at prep head
// (residual READS g_S/g_D, so it must not zero them).
__device__ float g_a[B_ * C_];       // scale * (q[b]^T k_w)[c]   (atomic acc)
__device__ float g_qkb[B_];          // scale * q[b].k_b          (atomic acc)
__device__ float g_S[B_ * C_];       // attention-weighted channel sums (atomic)
__device__ float g_D[B_];            // exp-sum (atomic)
__device__ float g_M[C_ * C_];       // M[c,c'] = sum_e o_w[c,e] v_w[e,c']
__device__ float g_bias2[C_];        // o_w[c,:].v_b + o_b[c]

// ============================================================
// Kernel 1: prep. blocks [0,1024): fused q+a projection.
// blocks [1024,1088): M = o_w @ v_w and bias2.
// qa blocks also zero g_S/g_D for this replay.
// ============================================================
__global__ void __launch_bounds__(256) k_prep(
    const float* __restrict__ text, const float* __restrict__ q_w,
    const float* __restrict__ q_b,  const float* __restrict__ k_w,
    const float* __restrict__ k_b,  const float* __restrict__ v_w,
    const float* __restrict__ v_b,  const float* __restrict__ o_w,
    const float* __restrict__ o_b)
{
    int blk = blockIdx.x;
    int tid = threadIdx.x, warp = tid >> 5, lane = tid & 31;

    if (blk < QA_BLOCKS) {
        // ---------------- qa part ----------------
        int b = blk & 31, slice = blk >> 5;
        __shared__ float txt[T_];
        __shared__ float q_sm[8];

        // zero g_S/g_D for this replay (1024 blocks x 14 = 14336 exact)
        if (tid < 14) g_S[blk * 14 + tid] = 0.f;
        if (slice == 0 && tid == 14) g_D[b] = 0.f;

        if (tid < T_ / 4)    // 192 float4s
            reinterpret_cast<float4*>(txt)[tid] =
                reinterpret_cast<const float4*>(text + (size_t)b * T_)[tid];
        __syncthreads();

        int eBase = slice * 8;
        {
            int e = eBase + warp;
            const float4* w = reinterpret_cast<const float4*>(q_w + (size_t)e * T_);
            const float4* tt = reinterpret_cast<const float4*>(txt);
            float acc = 0.f;
            #pragma unroll
            for (int it = 0; it < 6; ++it) {          // 6*32*4 = 768 exact
                int j = it * 32 + lane;
                float4 x = w[j], y = tt[j];
                acc += x.x * y.x + x.y * y.y + x.z * y.z + x.w * y.w;
            }
            #pragma unroll
            for (int o = 16; o > 0; o >>= 1) acc += __shfl_down_sync(0xffffffffu, acc, o);
            if (lane == 0) q_sm[warp] = acc + q_b[e];
        }
        __syncthreads();

        if (warp == 0) {
            float p = (lane < 8) ? q_sm[lane] * k_b[eBase + lane] : 0.f;
            p += __shfl_xor_sync(0xffffffffu, p, 4);
            p += __shfl_xor_sync(0xffffffffu, p, 2);
            p += __shfl_xor_sync(0xffffffffu, p, 1);
            if (lane == 0) atomicAdd(&g_qkb[b], SCALE * p);
        }

        {
            int c0 = tid, c1 = tid + 256;       // c1 valid iff tid < 192
            float acc0 = 0.f, acc1 = 0.f;
            if (tid < 192) {
                #pragma unroll
                for (int j = 0; j < 8; ++j) {
                    float qv = q_sm[j];
                    const float* row = k_w + (size_t)(eBase + j) * C_;
                    acc0 += qv * row[c0];
                    acc1 += qv * row[c1];
                }
                atomicAdd(&g_a[b * C_ + c1], SCALE * acc1);
            } else {
                #pragma unroll
                for (int j = 0; j < 8; ++j)
                    acc0 += q_sm[j] * k_w[(size_t)(eBase + j) * C_ + c0];
            }
            atomicAdd(&g_a[b * C_ + c0], SCALE * acc0);
        }
    } else {
        // ---------------- M part ----------------
        int m = blk - QA_BLOCKS;          // 0..63
        int cBase = m * CPM;              // 7 rows of M
        __shared__ float o_sm[CPM * E_];  // 7*256 floats = 7 KB

        for (int i = tid; i < CPM * E_; i += 256) {
            int cr = i >> 8, e = i & 255;
            o_sm[i] = o_w[(size_t)(cBase + cr) * E_ + e];
        }
        __syncthreads();

        // each thread: columns c0 = tid, c1 = tid+256 (if tid<192)
        int c0 = tid, c1 = tid + 256;
        float acc0[CPM], acc1[CPM];
        #pragma unroll
        for (int j = 0; j < CPM; ++j) { acc0[j] = 0.f; acc1[j] = 0.f; }

        if (tid < 192) {
            #pragma unroll 4
            for (int e = 0; e < E_; ++e) {
                float v0 = v_w[(size_t)e * C_ + c0];
                float v1 = v_w[(size_t)e * C_ + c1];
                #pragma unroll
                for (int j = 0; j < CPM; ++j) {
                    float ov = o_sm[j * E_ + e];
                    acc0[j] += ov * v0;
                    acc1[j] += ov * v1;
                }
            }
            #pragma unroll
            for (int j = 0; j < CPM; ++j)
                g_M[(size_t)(cBase + j) * C_ + c1] = acc1[j];
        } else {
            #pragma unroll 4
            for (int e = 0; e < E_; ++e) {
                float v0 = v_w[(size_t)e * C_ + c0];
                #pragma unroll
                for (int j = 0; j < CPM; ++j)
                    acc0[j] += o_sm[j * E_ + e] * v0;
            }
        }
        #pragma unroll
        for (int j = 0; j < CPM; ++j)
            g_M[(size_t)(cBase + j) * C_ + c0] = acc0[j];

        // bias2: warps 0..6 each handle one c row
        if (warp < CPM) {
            float p = 0.f;
            #pragma unroll
            for (int it = 0; it < 8; ++it) {
                int e = it * 32 + lane;
                p += o_sm[warp * E_ + e] * v_b[e];
            }
            #pragma unroll
            for (int o = 16; o > 0; o >>= 1) p += __shfl_down_sync(0xffffffffu, p, o);
            if (lane == 0) g_bias2[cBase + warp] = p + o_b[cBase + warp];
        }
    }
}

// ============================================================
// Kernel 2: all-register attention pass, one 16-pixel chunk per
// block. Thread layout: v = tid&3 (pixel quarter), k = tid>>2;
// thread owns channels it*64+k (it=0..6), pixels v*4..v*4+3.
// ============================================================
__global__ void __launch_bounds__(256) k_attn_pass(const float* __restrict__ img)
{
    int gx = blockIdx.x, b = blockIdx.y;
    int tid = threadIdx.x;
    int warp = tid >> 5, lane = tid & 31;
    int v = tid & 3, k = tid >> 2;

    __shared__ float a_sm[C_];
    __shared__ float red_s[128];        // [warp][16] partial logits
    __shared__ float e_sm[CHUNK];

    for (int c = tid; c < C_; c += 256) a_sm[c] = g_a[b * C_ + c];
    float qkb = g_qkb[b];

    // issue image loads immediately (independent of a_sm)
    const float* base = img + ((size_t)b * C_ + k) * N_ + gx * CHUNK + v * 4;
    float4 r[7];
    #pragma unroll
    for (int it = 0; it < 7; ++it)
        r[it] = *reinterpret_cast<const float4*>(base + (size_t)(it * 64) * N_);
    __syncthreads();

    // per-thread a values for its 7 channels
    float aq[7];
    #pragma unroll
    for (int it = 0; it < 7; ++it) aq[it] = a_sm[it * 64 + k];

    // ---- phase A partials from registers (28 FMA) ----
    float plx = 0.f, ply = 0.f, plz = 0.f, plw = 0.f;
    #pragma unroll
    for (int it = 0; it < 7; ++it) {
        float a = aq[it];
        plx += a * r[it].x; ply += a * r[it].y;
        plz += a * r[it].z; plw += a * r[it].w;
    }

    // ---- reduce partials over lanes sharing v (strides 4,8,16) ----
    #pragma unroll
    for (int m = 4; m <= 16; m <<= 1) {
        plx += __shfl_xor_sync(0xffffffffu, plx, m);
        ply += __shfl_xor_sync(0xffffffffu, ply, m);
        plz += __shfl_xor_sync(0xffffffffu, plz, m);
        plw += __shfl_xor_sync(0xffffffffu, plw, m);
    }
    if (lane < 4) {      // lane == v for lanes 0..3
        float4 p4 = make_float4(plx, ply, plz, plw);
        reinterpret_cast<float4*>(red_s)[warp * 4 + lane] = p4;
    }
    __syncthreads();

    // ---- exp over 16 pixels + D flush ----
    if (tid < 16) {
        float lg = 0.f;
        #pragma unroll
        for (int w = 0; w < 8; ++w) lg += red_s[w * 16 + tid];
        float e = __expf(lg + qkb);
        e_sm[tid] = e;
        float d = e;
        d += __shfl_xor_sync(0xffffu, d, 8);
        d += __shfl_xor_sync(0xffffu, d, 4);
        d += __shfl_xor_sync(0xffffu, d, 2);
        d += __shfl_xor_sync(0xffffu, d, 1);
        if (tid == 0) atomicAdd(&g_D[b], d);
    }
    __syncthreads();

    // ---- phase B from registers (28 FMA) + flush ----
    float4 e4 = reinterpret_cast<const float4*>(e_sm)[v];
    #pragma unroll
    for (int it = 0; it < 7; ++it) {
        float s = r[it].x * e4.x + r[it].y * e4.y
                + r[it].z * e4.z + r[it].w * e4.w;
        s += __shfl_xor_sync(0xffffffffu, s, 1);
        s += __shfl_xor_sync(0xffffffffu, s, 2);
        if (v == 0) atomicAdd(&g_S[b * C_ + it * 64 + k], s);
    }
}

// ============================================================
// Kernel 3: fused out-projection + residual via M:
// out[b,c,:] = img + (M[c,:].S[b,:])/D[b] + bias2[c].
// Barrier-free per-warp dot (M row + S row are L2-hot).
// Tail: re-zero g_a/g_qkb for the next replay.
// ============================================================
__global__ void __launch_bounds__(256) k_residual(const float* __restrict__ img,
                                                  float* __restrict__ out)
{
    int blk = blockIdx.x;              // 0 .. B_*C_-1
    int b = blk / C_, c = blk - b * C_;
    int tid = threadIdx.x, lane = tid & 31;

    const float4* src = reinterpret_cast<const float4*>(img) + (size_t)blk * (N_ / 4);
    float4* dst = reinterpret_cast<float4*>(out) + (size_t)blk * (N_ / 4);

    // issue image loads first (784 float4: 3 per thread + 16-thread tail)
    float4 r0 = src[tid];
    float4 r1 = src[tid + 256];
    float4 r2 = src[tid + 512];
    float4 r3;
    if (tid < 16) r3 = src[tid + 768];

    // per-warp dot over c' (M row + S row are cache-hot)
    const float* Mr = g_M + (size_t)c * C_;
    const float* Sr = g_S + b * C_;
    float p = 0.f;
    #pragma unroll
    for (int it = 0; it < 14; ++it) {
        int e = it * 32 + lane;
        p += Mr[e] * Sr[e];
    }
    #pragma unroll
    for (int o = 16; o > 0; o >>= 1) p += __shfl_xor_sync(0xffffffffu, p, o);
    float add = p / g_D[b] + __ldg(&g_bias2[c]);

    // re-zero q/a accumulators for the next replay (one element per block)
    if (tid == 64) {
        g_a[blk] = 0.f;
        if (blk < B_) g_qkb[blk] = 0.f;
    }

    r0.x += add; r0.y += add; r0.z += add; r0.w += add;
    r1.x += add; r1.y += add; r1.z += add; r1.w += add;
    r2.x += add; r2.y += add; r2.z += add; r2.w += add;
    __stcs(dst + tid, r0);
    __stcs(dst + tid + 256, r1);
    __stcs(dst + tid + 512, r2);
    if (tid < 16) {
        r3.x += add; r3.y += add; r3.z += add; r3.w += add;
        __stcs(dst + tid + 768, r3);
    }
}

// ============================================================
extern "C" void kernel_launch(void* const* d_in, const int* in_sizes, int n_in,
                              void* d_out, int out_size)
{
    const float* text = (const float*)d_in[0];
    const float* img  = (const float*)d_in[1];
    const float* q_w  = (const float*)d_in[2];
    const float* q_b  = (const float*)d_in[3];
    const float* k_w  = (const float*)d_in[4];
    const float* k_b  = (const float*)d_in[5];
    const float* v_w  = (const float*)d_in[6];
    const float* v_b  = (const float*)d_in[7];
    const float* o_w  = (const float*)d_in[8];
    const float* o_b  = (const float*)d_in[9];
    float* out = (float*)d_out;

    k_prep<<<QA_BLOCKS + M_BLOCKS, 256>>>(text, q_w, q_b, k_w, k_b,
                                          v_w, v_b, o_w, o_b);
    k_attn_pass<<<dim3(GX, B_), 256>>>(img);
    k_residual<<<B_ * C_, 256>>>(img, out);
}

// round 15
// speedup vs baseline: 1.1450x; 1.1450x over previous
#include <cuda_runtime.h>
#include <cuda_bf16.h>
#include <cstdint>

// Problem shape (fixed by the dataset)
#define B_  32
#define T_  768
#define C_  448
#define E_  256
#define N_  3136          // H*W = 56*56
#define SCALE 0.0625f     // 1/sqrt(E)

#define CHUNK 16
#define GX 196                // pixel-groups per batch: 196*16 = 3136 exact

#define QA_BLOCKS (32 * B_)   // 1024 qa blocks
#define CPM 4                 // M rows per block
#define M_BLOCKS (C_ / CPM)   // 112 M blocks

// -------- device scratch (no allocations allowed) --------
// g_a/g_qkb zeroed in residual tail; g_S/g_D zeroed at prep head
// (residual READS g_S/g_D, so it must not zero them). g_M/g_bias2
// are plain stores (overwritten every replay).
__device__ float g_a[B_ * C_];       // scale * (q[b]^T k_w)[c]   (atomic acc)
__device__ float g_qkb[B_];          // scale * q[b].k_b          (atomic acc)
__device__ float g_S[B_ * C_];       // attention-weighted channel sums (atomic)
__device__ float g_D[B_];            // exp-sum (atomic)
__device__ float g_M[C_ * C_];       // M[c,c'] = sum_e o_w[c,e] v_w[e,c']
__device__ float g_bias2[C_];        // o_w[c,:].v_b + o_b[c]

// ============================================================
// Kernel 1: prep. blocks [0,1024): fused q+a projection.
// blocks [1024,1136): M = o_w @ v_w (4 rows/block) and bias2.
// qa blocks also zero g_S/g_D for this replay.
// ============================================================
__global__ void __launch_bounds__(256) k_prep(
    const float* __restrict__ text, const float* __restrict__ q_w,
    const float* __restrict__ q_b,  const float* __restrict__ k_w,
    const float* __restrict__ k_b,  const float* __restrict__ v_w,
    const float* __restrict__ v_b,  const float* __restrict__ o_w,
    const float* __restrict__ o_b)
{
    int blk = blockIdx.x;
    int tid = threadIdx.x, warp = tid >> 5, lane = tid & 31;

    if (blk < QA_BLOCKS) {
        // ---------------- qa part ----------------
        int b = blk & 31, slice = blk >> 5;
        __shared__ float txt[T_];
        __shared__ float q_sm[8];

        // zero g_S/g_D for this replay (1024 blocks x 14 = 14336 exact)
        if (tid < 14) g_S[blk * 14 + tid] = 0.f;
        if (slice == 0 && tid == 14) g_D[b] = 0.f;

        if (tid < T_ / 4)    // 192 float4s
            reinterpret_cast<float4*>(txt)[tid] =
                reinterpret_cast<const float4*>(text + (size_t)b * T_)[tid];
        __syncthreads();

        int eBase = slice * 8;
        {
            int e = eBase + warp;
            const float4* w = reinterpret_cast<const float4*>(q_w + (size_t)e * T_);
            const float4* tt = reinterpret_cast<const float4*>(txt);
            float acc = 0.f;
            #pragma unroll
            for (int it = 0; it < 6; ++it) {          // 6*32*4 = 768 exact
                int j = it * 32 + lane;
                float4 x = w[j], y = tt[j];
                acc += x.x * y.x + x.y * y.y + x.z * y.z + x.w * y.w;
            }
            #pragma unroll
            for (int o = 16; o > 0; o >>= 1) acc += __shfl_down_sync(0xffffffffu, acc, o);
            if (lane == 0) q_sm[warp] = acc + q_b[e];
        }
        __syncthreads();

        if (warp == 0) {
            float p = (lane < 8) ? q_sm[lane] * k_b[eBase + lane] : 0.f;
            p += __shfl_xor_sync(0xffffffffu, p, 4);
            p += __shfl_xor_sync(0xffffffffu, p, 2);
            p += __shfl_xor_sync(0xffffffffu, p, 1);
            if (lane == 0) atomicAdd(&g_qkb[b], SCALE * p);
        }

        {
            int c0 = tid, c1 = tid + 256;       // c1 valid iff tid < 192
            float acc0 = 0.f, acc1 = 0.f;
            if (tid < 192) {
                #pragma unroll
                for (int j = 0; j < 8; ++j) {
                    float qv = q_sm[j];
                    const float* row = k_w + (size_t)(eBase + j) * C_;
                    acc0 += qv * row[c0];
                    acc1 += qv * row[c1];
                }
                atomicAdd(&g_a[b * C_ + c1], SCALE * acc1);
            } else {
                #pragma unroll
                for (int j = 0; j < 8; ++j)
                    acc0 += q_sm[j] * k_w[(size_t)(eBase + j) * C_ + c0];
            }
            atomicAdd(&g_a[b * C_ + c0], SCALE * acc0);
        }
    } else {
        // ---------------- M part: 4 rows of M per block ----------------
        int m = blk - QA_BLOCKS;          // 0..111
        int cBase = m * CPM;
        __shared__ float o_sm[CPM * E_];  // 4*256 floats = 4 KB

        for (int i = tid; i < CPM * E_; i += 256) {
            int cr = i >> 8, e = i & 255;
            o_sm[i] = o_w[(size_t)(cBase + cr) * E_ + e];
        }
        __syncthreads();

        // each thread: columns c0 = tid, c1 = tid+256 (if tid<192)
        int c0 = tid, c1 = tid + 256;
        float a0[CPM], a1[CPM];
        #pragma unroll
        for (int j = 0; j < CPM; ++j) { a0[j] = 0.f; a1[j] = 0.f; }

        if (tid < 192) {
            #pragma unroll 8
            for (int e = 0; e < E_; ++e) {
                float v0 = v_w[(size_t)e * C_ + c0];
                float v1 = v_w[(size_t)e * C_ + c1];
                #pragma unroll
                for (int j = 0; j < CPM; ++j) {
                    float ov = o_sm[j * E_ + e];
                    a0[j] += ov * v0;
                    a1[j] += ov * v1;
                }
            }
            #pragma unroll
            for (int j = 0; j < CPM; ++j)
                g_M[(size_t)(cBase + j) * C_ + c1] = a1[j];
        } else {
            #pragma unroll 8
            for (int e = 0; e < E_; ++e) {
                float v0 = v_w[(size_t)e * C_ + c0];
                #pragma unroll
                for (int j = 0; j < CPM; ++j)
                    a0[j] += o_sm[j * E_ + e] * v0;
            }
        }
        #pragma unroll
        for (int j = 0; j < CPM; ++j)
            g_M[(size_t)(cBase + j) * C_ + c0] = a0[j];

        // bias2: warps 0..3 each handle one c row
        if (warp < CPM) {
            float p = 0.f;
            #pragma unroll
            for (int it = 0; it < 8; ++it) {
                int e = it * 32 + lane;
                p += o_sm[warp * E_ + e] * v_b[e];
            }
            #pragma unroll
            for (int o = 16; o > 0; o >>= 1) p += __shfl_down_sync(0xffffffffu, p, o);
            if (lane == 0) g_bias2[cBase + warp] = p + o_b[cBase + warp];
        }
    }
}

// ============================================================
// Kernel 2: all-register attention pass, one 16-pixel chunk per
// block. Thread layout: v = tid&3 (pixel quarter), k = tid>>2;
// thread owns channels it*64+k (it=0..6), pixels v*4..v*4+3.
// ============================================================
__global__ void __launch_bounds__(256) k_attn_pass(const float* __restrict__ img)
{
    int gx = blockIdx.x, b = blockIdx.y;
    int tid = threadIdx.x;
    int warp = tid >> 5, lane = tid & 31;
    int v = tid & 3, k = tid >> 2;

    __shared__ float a_sm[C_];
    __shared__ float red_s[128];        // [warp][16] partial logits
    __shared__ float e_sm[CHUNK];

    for (int c = tid; c < C_; c += 256) a_sm[c] = g_a[b * C_ + c];
    float qkb = g_qkb[b];

    // issue image loads immediately (independent of a_sm)
    const float* base = img + ((size_t)b * C_ + k) * N_ + gx * CHUNK + v * 4;
    float4 r[7];
    #pragma unroll
    for (int it = 0; it < 7; ++it)
        r[it] = *reinterpret_cast<const float4*>(base + (size_t)(it * 64) * N_);
    __syncthreads();

    // per-thread a values for its 7 channels
    float aq[7];
    #pragma unroll
    for (int it = 0; it < 7; ++it) aq[it] = a_sm[it * 64 + k];

    // ---- phase A partials from registers (28 FMA) ----
    float plx = 0.f, ply = 0.f, plz = 0.f, plw = 0.f;
    #pragma unroll
    for (int it = 0; it < 7; ++it) {
        float a = aq[it];
        plx += a * r[it].x; ply += a * r[it].y;
        plz += a * r[it].z; plw += a * r[it].w;
    }

    // ---- reduce partials over lanes sharing v (strides 4,8,16) ----
    #pragma unroll
    for (int m = 4; m <= 16; m <<= 1) {
        plx += __shfl_xor_sync(0xffffffffu, plx, m);
        ply += __shfl_xor_sync(0xffffffffu, ply, m);
        plz += __shfl_xor_sync(0xffffffffu, plz, m);
        plw += __shfl_xor_sync(0xffffffffu, plw, m);
    }
    if (lane < 4) {      // lane == v for lanes 0..3
        float4 p4 = make_float4(plx, ply, plz, plw);
        reinterpret_cast<float4*>(red_s)[warp * 4 + lane] = p4;
    }
    __syncthreads();

    // ---- exp over 16 pixels + D flush ----
    if (tid < 16) {
        float lg = 0.f;
        #pragma unroll
        for (int w = 0; w < 8; ++w) lg += red_s[w * 16 + tid];
        float e = __expf(lg + qkb);
        e_sm[tid] = e;
        float d = e;
        d += __shfl_xor_sync(0xffffu, d, 8);
        d += __shfl_xor_sync(0xffffu, d, 4);
        d += __shfl_xor_sync(0xffffu, d, 2);
        d += __shfl_xor_sync(0xffffu, d, 1);
        if (tid == 0) atomicAdd(&g_D[b], d);
    }
    __syncthreads();

    // ---- phase B from registers (28 FMA) + flush ----
    float4 e4 = reinterpret_cast<const float4*>(e_sm)[v];
    #pragma unroll
    for (int it = 0; it < 7; ++it) {
        float s = r[it].x * e4.x + r[it].y * e4.y
                + r[it].z * e4.z + r[it].w * e4.w;
        s += __shfl_xor_sync(0xffffffffu, s, 1);
        s += __shfl_xor_sync(0xffffffffu, s, 2);
        if (v == 0) atomicAdd(&g_S[b * C_ + it * 64 + k], s);
    }
}

// ============================================================
// Kernel 3: fused out-projection + residual via M:
// out[b,c,:] = img + (M[c,:].S[b,:])/D[b] + bias2[c].
// Barrier-free per-warp dot (M row + S row are L2-hot).
// Tail: re-zero g_a/g_qkb for the next replay.
// ============================================================
__global__ void __launch_bounds__(256) k_residual(const float* __restrict__ img,
                                                  float* __restrict__ out)
{
    int blk = blockIdx.x;              // 0 .. B_*C_-1
    int b = blk / C_, c = blk - b * C_;
    int tid = threadIdx.x, lane = tid & 31;

    const float4* src = reinterpret_cast<const float4*>(img) + (size_t)blk * (N_ / 4);
    float4* dst = reinterpret_cast<float4*>(out) + (size_t)blk * (N_ / 4);

    // issue image loads first (784 float4: 3 per thread + 16-thread tail)
    float4 r0 = src[tid];
    float4 r1 = src[tid + 256];
    float4 r2 = src[tid + 512];
    float4 r3;
    if (tid < 16) r3 = src[tid + 768];

    // per-warp dot over c' (M row + S row are cache-hot)
    const float* Mr = g_M + (size_t)c * C_;
    const float* Sr = g_S + b * C_;
    float p = 0.f;
    #pragma unroll
    for (int it = 0; it < 14; ++it) {
        int e = it * 32 + lane;
        p += Mr[e] * Sr[e];
    }
    #pragma unroll
    for (int o = 16; o > 0; o >>= 1) p += __shfl_xor_sync(0xffffffffu, p, o);
    float add = p / g_D[b] + __ldg(&g_bias2[c]);

    // re-zero q/a accumulators for the next replay (one element per block)
    if (tid == 64) {
        g_a[blk] = 0.f;
        if (blk < B_) g_qkb[blk] = 0.f;
    }

    r0.x += add; r0.y += add; r0.z += add; r0.w += add;
    r1.x += add; r1.y += add; r1.z += add; r1.w += add;
    r2.x += add; r2.y += add; r2.z += add; r2.w += add;
    __stcs(dst + tid, r0);
    __stcs(dst + tid + 256, r1);
    __stcs(dst + tid + 512, r2);
    if (tid < 16) {
        r3.x += add; r3.y += add; r3.z += add; r3.w += add;
        __stcs(dst + tid + 768, r3);
    }
}

// ============================================================
extern "C" void kernel_launch(void* const* d_in, const int* in_sizes, int n_in,
                              void* d_out, int out_size)
{
    const float* text = (const float*)d_in[0];
    const float* img  = (const float*)d_in[1];
    const float* q_w  = (const float*)d_in[2];
    const float* q_b  = (const float*)d_in[3];
    const float* k_w  = (const float*)d_in[4];
    const float* k_b  = (const float*)d_in[5];
    const float* v_w  = (const float*)d_in[6];
    const float* v_b  = (const float*)d_in[7];
    const float* o_w  = (const float*)d_in[8];
    const float* o_b  = (const float*)d_in[9];
    float* out = (float*)d_out;

    k_prep<<<QA_BLOCKS + M_BLOCKS, 256>>>(text, q_w, q_b, k_w, k_b,
                                          v_w, v_b, o_w, o_b);
    k_attn_pass<<<dim3(GX, B_), 256>>>(img);
    k_residual<<<B_ * C_, 256>>>(img, out);
}

// round 16
// speedup vs baseline: 1.5644x; 1.3663x over previous
#include <cuda_runtime.h>
#include <cuda_bf16.h>
#include <cstdint>

// Problem shape (fixed by the dataset)
#define B_  32
#define T_  768
#define C_  448
#define E_  256
#define N_  3136          // H*W = 56*56
#define SCALE 0.0625f     // 1/sqrt(E)

#define CHUNK 16
#define GX 196                // pixel-groups per batch: 196*16 = 3136 exact
#define MB  C_                // 448 M blocks (one M row each), front of attn grid

// -------- device scratch (no allocations allowed) --------
// g_a/g_qkb zeroed in residual tail; g_S/g_D zeroed in k_qa.
// g_M/g_bias2 are plain stores (rewritten every replay).
__device__ float g_a[B_ * C_];       // scale * (q[b]^T k_w)[c]   (atomic acc)
__device__ float g_qkb[B_];          // scale * q[b].k_b          (atomic acc)
__device__ float g_S[B_ * C_];       // attention-weighted channel sums (atomic)
__device__ float g_D[B_];            // exp-sum (atomic)
__device__ float g_M[C_ * C_];       // M[c,c'] = sum_e o_w[c,e] v_w[e,c']
__device__ float g_bias2[C_];        // o_w[c,:].v_b + o_b[c]

// ============================================================
// Kernel 1: fused q-projection + a-projection (proven R11 form).
// grid (32, B_): block computes q[e] for its 8-e slice, then
// partial a[b,c] and qkb[b] via atomicAdd. Also zeroes g_S/g_D.
// ============================================================
__global__ void __launch_bounds__(256) k_qa(
    const float* __restrict__ text, const float* __restrict__ q_w,
    const float* __restrict__ q_b,  const float* __restrict__ k_w,
    const float* __restrict__ k_b)
{
    int slice = blockIdx.x, b = blockIdx.y;
    int tid = threadIdx.x, warp = tid >> 5, lane = tid & 31;
    __shared__ float txt[T_];
    __shared__ float q_sm[8];

    // zero g_S/g_D for this replay (1024 blocks x 14 = 14336 exact)
    {
        int blk = b * 32 + slice;
        if (tid < 14) g_S[blk * 14 + tid] = 0.f;
        if (slice == 0 && tid == 14) g_D[b] = 0.f;
    }

    if (tid < T_ / 4)    // 192 float4s
        reinterpret_cast<float4*>(txt)[tid] =
            reinterpret_cast<const float4*>(text + (size_t)b * T_)[tid];
    __syncthreads();

    int eBase = slice * 8;
    // warp-per-e q dot: single 6-load batch + one shuffle chain
    {
        int e = eBase + warp;
        const float4* w = reinterpret_cast<const float4*>(q_w + (size_t)e * T_);
        const float4* tt = reinterpret_cast<const float4*>(txt);
        float acc = 0.f;
        #pragma unroll
        for (int it = 0; it < 6; ++it) {          // 6*32*4 = 768 exact
            int j = it * 32 + lane;
            float4 x = w[j], y = tt[j];
            acc += x.x * y.x + x.y * y.y + x.z * y.z + x.w * y.w;
        }
        #pragma unroll
        for (int o = 16; o > 0; o >>= 1) acc += __shfl_down_sync(0xffffffffu, acc, o);
        if (lane == 0) q_sm[warp] = acc + q_b[e];
    }
    __syncthreads();

    // qkb partial: 8 products, reduced in warp 0
    if (warp == 0) {
        float p = (lane < 8) ? q_sm[lane] * k_b[eBase + lane] : 0.f;
        p += __shfl_xor_sync(0xffffffffu, p, 4);
        p += __shfl_xor_sync(0xffffffffu, p, 2);
        p += __shfl_xor_sync(0xffffffffu, p, 1);
        if (lane == 0) atomicAdd(&g_qkb[b], SCALE * p);
    }

    // a[b,c] partial over this slice's 8 e-rows (k_w rows L2-hot across b)
    {
        int c0 = tid, c1 = tid + 256;       // c1 valid iff tid < 192
        float acc0 = 0.f, acc1 = 0.f;
        if (tid < 192) {
            #pragma unroll
            for (int j = 0; j < 8; ++j) {
                float qv = q_sm[j];
                const float* row = k_w + (size_t)(eBase + j) * C_;
                acc0 += qv * row[c0];
                acc1 += qv * row[c1];
            }
            atomicAdd(&g_a[b * C_ + c1], SCALE * acc1);
        } else {
            #pragma unroll
            for (int j = 0; j < 8; ++j)
                acc0 += q_sm[j] * k_w[(size_t)(eBase + j) * C_ + c0];
        }
        atomicAdd(&g_a[b * C_ + c0], SCALE * acc0);
    }
}

// ============================================================
// Kernel 2: blocks [0,448): M = o_w @ v_w (one row each) +
// bias2 — latency/L2-bound, hidden under the DRAM-bound attn
// blocks [448, 448+6272) running concurrently.
// ============================================================
__global__ void __launch_bounds__(256) k_attn(
    const float* __restrict__ img,
    const float* __restrict__ v_w, const float* __restrict__ v_b,
    const float* __restrict__ o_w, const float* __restrict__ o_b)
{
    int blk = blockIdx.x;
    int tid = threadIdx.x;
    int warp = tid >> 5, lane = tid & 31;

    if (blk < MB) {
        // ---------------- M row c = blk ----------------
        int c = blk;
        __shared__ float o_sm[E_];
        o_sm[tid] = o_w[(size_t)c * E_ + tid];
        __syncthreads();

        int c0 = tid, c1 = tid + 256;     // c1 valid iff tid < 192
        float a0 = 0.f, a1 = 0.f;
        if (tid < 192) {
            #pragma unroll 16
            for (int e = 0; e < E_; ++e) {
                float ov = o_sm[e];
                a0 += ov * v_w[(size_t)e * C_ + c0];
                a1 += ov * v_w[(size_t)e * C_ + c1];
            }
            g_M[(size_t)c * C_ + c1] = a1;
        } else {
            #pragma unroll 16
            for (int e = 0; e < E_; ++e)
                a0 += o_sm[e] * v_w[(size_t)e * C_ + c0];
        }
        g_M[(size_t)c * C_ + c0] = a0;

        // bias2[c] = o_w[c,:].v_b + o_b[c]  (warp 0)
        if (warp == 0) {
            float p = 0.f;
            #pragma unroll
            for (int it = 0; it < 8; ++it) {
                int e = it * 32 + lane;
                p += o_sm[e] * v_b[e];
            }
            #pragma unroll
            for (int o = 16; o > 0; o >>= 1) p += __shfl_down_sync(0xffffffffu, p, o);
            if (lane == 0) g_bias2[c] = p + o_b[c];
        }
        return;
    }

    // ---------------- attention chunk ----------------
    int idx = blk - MB;
    int b = idx / GX, gx = idx - b * GX;
    int v = tid & 3, k = tid >> 2;

    __shared__ float a_sm[C_];
    __shared__ float red_s[128];        // [warp][16] partial logits
    __shared__ float e_sm[CHUNK];

    for (int c = tid; c < C_; c += 256) a_sm[c] = g_a[b * C_ + c];
    float qkb = g_qkb[b];

    // issue image loads immediately (independent of a_sm)
    const float* base = img + ((size_t)b * C_ + k) * N_ + gx * CHUNK + v * 4;
    float4 r[7];
    #pragma unroll
    for (int it = 0; it < 7; ++it)
        r[it] = *reinterpret_cast<const float4*>(base + (size_t)(it * 64) * N_);
    __syncthreads();

    // per-thread a values for its 7 channels
    float aq[7];
    #pragma unroll
    for (int it = 0; it < 7; ++it) aq[it] = a_sm[it * 64 + k];

    // ---- phase A partials from registers (28 FMA) ----
    float plx = 0.f, ply = 0.f, plz = 0.f, plw = 0.f;
    #pragma unroll
    for (int it = 0; it < 7; ++it) {
        float a = aq[it];
        plx += a * r[it].x; ply += a * r[it].y;
        plz += a * r[it].z; plw += a * r[it].w;
    }

    // ---- reduce partials over lanes sharing v (strides 4,8,16) ----
    #pragma unroll
    for (int m = 4; m <= 16; m <<= 1) {
        plx += __shfl_xor_sync(0xffffffffu, plx, m);
        ply += __shfl_xor_sync(0xffffffffu, ply, m);
        plz += __shfl_xor_sync(0xffffffffu, plz, m);
        plw += __shfl_xor_sync(0xffffffffu, plw, m);
    }
    if (lane < 4) {      // lane == v for lanes 0..3
        float4 p4 = make_float4(plx, ply, plz, plw);
        reinterpret_cast<float4*>(red_s)[warp * 4 + lane] = p4;
    }
    __syncthreads();

    // ---- exp over 16 pixels + D flush ----
    if (tid < 16) {
        float lg = 0.f;
        #pragma unroll
        for (int w = 0; w < 8; ++w) lg += red_s[w * 16 + tid];
        float e = __expf(lg + qkb);
        e_sm[tid] = e;
        float d = e;
        d += __shfl_xor_sync(0xffffu, d, 8);
        d += __shfl_xor_sync(0xffffu, d, 4);
        d += __shfl_xor_sync(0xffffu, d, 2);
        d += __shfl_xor_sync(0xffffu, d, 1);
        if (tid == 0) atomicAdd(&g_D[b], d);
    }
    __syncthreads();

    // ---- phase B from registers (28 FMA) + flush ----
    float4 e4 = reinterpret_cast<const float4*>(e_sm)[v];
    #pragma unroll
    for (int it = 0; it < 7; ++it) {
        float s = r[it].x * e4.x + r[it].y * e4.y
                + r[it].z * e4.z + r[it].w * e4.w;
        s += __shfl_xor_sync(0xffffffffu, s, 1);
        s += __shfl_xor_sync(0xffffffffu, s, 2);
        if (v == 0) atomicAdd(&g_S[b * C_ + it * 64 + k], s);
    }
}

// ============================================================
// Kernel 3: fused out-projection + residual via M:
// out[b,c,:] = img + (M[c,:].S[b,:])/D[b] + bias2[c].
// Barrier-free per-warp dot (M row + S row are L2-hot).
// Tail: re-zero g_a/g_qkb for the next replay.
// ============================================================
__global__ void __launch_bounds__(256) k_residual(const float* __restrict__ img,
                                                  float* __restrict__ out)
{
    int blk = blockIdx.x;              // 0 .. B_*C_-1
    int b = blk / C_, c = blk - b * C_;
    int tid = threadIdx.x, lane = tid & 31;

    const float4* src = reinterpret_cast<const float4*>(img) + (size_t)blk * (N_ / 4);
    float4* dst = reinterpret_cast<float4*>(out) + (size_t)blk * (N_ / 4);

    // issue image loads first (784 float4: 3 per thread + 16-thread tail)
    float4 r0 = src[tid];
    float4 r1 = src[tid + 256];
    float4 r2 = src[tid + 512];
    float4 r3;
    if (tid < 16) r3 = src[tid + 768];

    // per-warp dot over c' (M row + S row are cache-hot)
    const float* Mr = g_M + (size_t)c * C_;
    const float* Sr = g_S + b * C_;
    float p = 0.f;
    #pragma unroll
    for (int it = 0; it < 14; ++it) {
        int e = it * 32 + lane;
        p += Mr[e] * Sr[e];
    }
    #pragma unroll
    for (int o = 16; o > 0; o >>= 1) p += __shfl_xor_sync(0xffffffffu, p, o);
    float add = p / g_D[b] + __ldg(&g_bias2[c]);

    // re-zero q/a accumulators for the next replay (one element per block)
    if (tid == 64) {
        g_a[blk] = 0.f;
        if (blk < B_) g_qkb[blk] = 0.f;
    }

    r0.x += add; r0.y += add; r0.z += add; r0.w += add;
    r1.x += add; r1.y += add; r1.z += add; r1.w += add;
    r2.x += add; r2.y += add; r2.z += add; r2.w += add;
    __stcs(dst + tid, r0);
    __stcs(dst + tid + 256, r1);
    __stcs(dst + tid + 512, r2);
    if (tid < 16) {
        r3.x += add; r3.y += add; r3.z += add; r3.w += add;
        __stcs(dst + tid + 768, r3);
    }
}

// ============================================================
extern "C" void kernel_launch(void* const* d_in, const int* in_sizes, int n_in,
                              void* d_out, int out_size)
{
    const float* text = (const float*)d_in[0];
    const float* img  = (const float*)d_in[1];
    const float* q_w  = (const float*)d_in[2];
    const float* q_b  = (const float*)d_in[3];
    const float* k_w  = (const float*)d_in[4];
    const float* k_b  = (const float*)d_in[5];
    const float* v_w  = (const float*)d_in[6];
    const float* v_b  = (const float*)d_in[7];
    const float* o_w  = (const float*)d_in[8];
    const float* o_b  = (const float*)d_in[9];
    float* out = (float*)d_out;

    k_qa<<<dim3(32, B_), 256>>>(text, q_w, q_b, k_w, k_b);
    k_attn<<<MB + GX * B_, 256>>>(img, v_w, v_b, o_w, o_b);
    k_residual<<<B_ * C_, 256>>>(img, out);
}

// round 17
// speedup vs baseline: 1.8380x; 1.1749x over previous
#include <cuda_runtime.h>
#include <cuda_bf16.h>
#include <cstdint>

// Problem shape (fixed by the dataset)
#define B_  32
#define T_  768
#define C_  448
#define E_  256
#define N_  3136          // H*W = 56*56
#define SCALE 0.0625f     // 1/sqrt(E)

#define CHUNK 16
#define GX 196                // pixel-groups per batch: 196*16 = 3136 exact

// -------- device scratch (no allocations allowed) --------
// Zero-initialized statics; re-zeroed at the tail of k_residual so every
// graph replay sees clean state.
__device__ float g_a[B_ * C_];       // scale * (q[b]^T k_w)[c]   (atomic acc)
__device__ float g_qkb[B_];          // scale * q[b].k_b          (atomic acc)
__device__ float g_S[B_ * C_];       // attention-weighted channel sums (atomic)
__device__ float g_D[B_];            // exp-sum (atomic)
__device__ float g_pooled[B_ * E_];  // pooled (already /D, +v_b)

// ============================================================
// Kernel 1: fused q+a projection, single-latency-round version.
// grid (32, B_). All independent load streams (q_w row, k_w
// rows, txt) are issued up-front; compute happens after one
// memory round instead of three.
// ============================================================
__global__ void __launch_bounds__(256) k_qa(
    const float* __restrict__ text, const float* __restrict__ q_w,
    const float* __restrict__ q_b,  const float* __restrict__ k_w,
    const float* __restrict__ k_b)
{
    int slice = blockIdx.x, b = blockIdx.y;
    int tid = threadIdx.x, warp = tid >> 5, lane = tid & 31;
    __shared__ float txt[T_];
    __shared__ float q_sm[8];

    int eBase = slice * 8;
    int e = eBase + warp;

    // ---- issue ALL independent loads up-front ----
    // (a) q_w row for this warp's e: 6 float4
    const float4* wrow = reinterpret_cast<const float4*>(q_w + (size_t)e * T_);
    float4 wx0 = wrow[lane];
    float4 wx1 = wrow[32 + lane];
    float4 wx2 = wrow[64 + lane];
    float4 wx3 = wrow[96 + lane];
    float4 wx4 = wrow[128 + lane];
    float4 wx5 = wrow[160 + lane];

    // (b) k_w values for this thread's columns (8 rows x up to 2 cols)
    int c0 = tid, c1 = tid + 256;         // c1 valid iff tid < 192
    float kw0[8], kw1[8];
    if (tid < 192) {
        #pragma unroll
        for (int j = 0; j < 8; ++j) {
            const float* row = k_w + (size_t)(eBase + j) * C_;
            kw0[j] = row[c0];
            kw1[j] = row[c1];
        }
    } else {
        #pragma unroll
        for (int j = 0; j < 8; ++j)
            kw0[j] = k_w[(size_t)(eBase + j) * C_ + c0];
    }

    // (c) txt into smem (192 float4)
    if (tid < T_ / 4)
        reinterpret_cast<float4*>(txt)[tid] =
            reinterpret_cast<const float4*>(text + (size_t)b * T_)[tid];

    // zero g_S/g_D for this replay (1024 blocks x 14 = 14336 exact)
    {
        int blk = b * 32 + slice;
        if (tid >= 240 && tid < 254) g_S[blk * 14 + (tid - 240)] = 0.f;
        if (slice == 0 && tid == 254) g_D[b] = 0.f;
    }
    __syncthreads();

    // ---- q dot from registers vs txt smem ----
    {
        const float4* tt = reinterpret_cast<const float4*>(txt);
        float acc = 0.f;
        float4 y;
        y = tt[lane];        acc += wx0.x*y.x + wx0.y*y.y + wx0.z*y.z + wx0.w*y.w;
        y = tt[32 + lane];   acc += wx1.x*y.x + wx1.y*y.y + wx1.z*y.z + wx1.w*y.w;
        y = tt[64 + lane];   acc += wx2.x*y.x + wx2.y*y.y + wx2.z*y.z + wx2.w*y.w;
        y = tt[96 + lane];   acc += wx3.x*y.x + wx3.y*y.y + wx3.z*y.z + wx3.w*y.w;
        y = tt[128 + lane];  acc += wx4.x*y.x + wx4.y*y.y + wx4.z*y.z + wx4.w*y.w;
        y = tt[160 + lane];  acc += wx5.x*y.x + wx5.y*y.y + wx5.z*y.z + wx5.w*y.w;
        #pragma unroll
        for (int o = 16; o > 0; o >>= 1) acc += __shfl_down_sync(0xffffffffu, acc, o);
        if (lane == 0) q_sm[warp] = acc + q_b[e];
    }
    __syncthreads();

    // qkb partial: 8 products, reduced in warp 0
    if (warp == 0) {
        float p = (lane < 8) ? q_sm[lane] * k_b[eBase + lane] : 0.f;
        p += __shfl_xor_sync(0xffffffffu, p, 4);
        p += __shfl_xor_sync(0xffffffffu, p, 2);
        p += __shfl_xor_sync(0xffffffffu, p, 1);
        if (lane == 0) atomicAdd(&g_qkb[b], SCALE * p);
    }

    // a[b,c] partial from prefetched k_w registers
    {
        float acc0 = 0.f, acc1 = 0.f;
        if (tid < 192) {
            #pragma unroll
            for (int j = 0; j < 8; ++j) {
                float qv = q_sm[j];
                acc0 += qv * kw0[j];
                acc1 += qv * kw1[j];
            }
            atomicAdd(&g_a[b * C_ + c1], SCALE * acc1);
        } else {
            #pragma unroll
            for (int j = 0; j < 8; ++j) acc0 += q_sm[j] * kw0[j];
        }
        atomicAdd(&g_a[b * C_ + c0], SCALE * acc0);
    }
}

// ============================================================
// Kernel 2: all-register attention pass, one 16-pixel chunk per
// block (identical to the 102.9us baseline).
// ============================================================
__global__ void __launch_bounds__(256) k_attn_pass(const float* __restrict__ img)
{
    int gx = blockIdx.x, b = blockIdx.y;
    int tid = threadIdx.x;
    int warp = tid >> 5, lane = tid & 31;
    int v = tid & 3, k = tid >> 2;

    __shared__ float a_sm[C_];
    __shared__ float red_s[128];        // [warp][16] partial logits
    __shared__ float e_sm[CHUNK];

    for (int c = tid; c < C_; c += 256) a_sm[c] = g_a[b * C_ + c];
    float qkb = g_qkb[b];

    // issue image loads immediately (independent of a_sm)
    const float* base = img + ((size_t)b * C_ + k) * N_ + gx * CHUNK + v * 4;
    float4 r[7];
    #pragma unroll
    for (int it = 0; it < 7; ++it)
        r[it] = *reinterpret_cast<const float4*>(base + (size_t)(it * 64) * N_);
    __syncthreads();

    // per-thread a values for its 7 channels
    float aq[7];
    #pragma unroll
    for (int it = 0; it < 7; ++it) aq[it] = a_sm[it * 64 + k];

    // ---- phase A partials from registers (28 FMA) ----
    float plx = 0.f, ply = 0.f, plz = 0.f, plw = 0.f;
    #pragma unroll
    for (int it = 0; it < 7; ++it) {
        float a = aq[it];
        plx += a * r[it].x; ply += a * r[it].y;
        plz += a * r[it].z; plw += a * r[it].w;
    }

    // ---- reduce partials over lanes sharing v (strides 4,8,16) ----
    #pragma unroll
    for (int m = 4; m <= 16; m <<= 1) {
        plx += __shfl_xor_sync(0xffffffffu, plx, m);
        ply += __shfl_xor_sync(0xffffffffu, ply, m);
        plz += __shfl_xor_sync(0xffffffffu, plz, m);
        plw += __shfl_xor_sync(0xffffffffu, plw, m);
    }
    if (lane < 4) {      // lane == v for lanes 0..3
        float4 p4 = make_float4(plx, ply, plz, plw);
        reinterpret_cast<float4*>(red_s)[warp * 4 + lane] = p4;
    }
    __syncthreads();

    // ---- exp over 16 pixels + D flush ----
    if (tid < 16) {
        float lg = 0.f;
        #pragma unroll
        for (int w = 0; w < 8; ++w) lg += red_s[w * 16 + tid];
        float e = __expf(lg + qkb);
        e_sm[tid] = e;
        float d = e;
        d += __shfl_xor_sync(0xffffu, d, 8);
        d += __shfl_xor_sync(0xffffu, d, 4);
        d += __shfl_xor_sync(0xffffu, d, 2);
        d += __shfl_xor_sync(0xffffu, d, 1);
        if (tid == 0) atomicAdd(&g_D[b], d);
    }
    __syncthreads();

    // ---- phase B from registers (28 FMA) + flush ----
    float4 e4 = reinterpret_cast<const float4*>(e_sm)[v];
    #pragma unroll
    for (int it = 0; it < 7; ++it) {
        float s = r[it].x * e4.x + r[it].y * e4.y
                + r[it].z * e4.z + r[it].w * e4.w;
        s += __shfl_xor_sync(0xffffffffu, s, 1);
        s += __shfl_xor_sync(0xffffffffu, s, 2);
        if (v == 0) atomicAdd(&g_S[b * C_ + it * 64 + k], s);
    }
}

// ============================================================
// Kernel 3: pooled = v_w @ (g_S/D) + v_b, single-latency-round.
// grid (B_, 16): warp-per-2e; the 28 v_w values are prefetched
// into registers before the s_sm load + barrier.
// ============================================================
__global__ void __launch_bounds__(256) k_pool(
    const float* __restrict__ v_w, const float* __restrict__ v_b)
{
    int b = blockIdx.x, slice = blockIdx.y;
    int tid = threadIdx.x, warp = tid >> 5, lane = tid & 31;
    __shared__ float s_sm[C_];
    __shared__ float invD_sm;

    int e0 = slice * 16 + warp * 2;

    // ---- prefetch v_w (independent of g_S) ----
    float w0v[14], w1v[14];
    const float* w0 = v_w + (size_t)(e0 + 0) * C_;
    const float* w1 = v_w + (size_t)(e0 + 1) * C_;
    #pragma unroll
    for (int it = 0; it < 14; ++it) {
        int c = it * 32 + lane;
        w0v[it] = w0[c];
        w1v[it] = w1[c];
    }

    // ---- load s and D ----
    s_sm[tid] = g_S[b * C_ + tid];
    if (tid < C_ - 256) s_sm[tid + 256] = g_S[b * C_ + tid + 256];
    if (tid == 0) invD_sm = 1.0f / g_D[b];
    __syncthreads();
    float invD = invD_sm;

    float acc0 = 0.f, acc1 = 0.f;
    #pragma unroll
    for (int it = 0; it < 14; ++it) {
        float sv = s_sm[it * 32 + lane];
        acc0 += w0v[it] * sv;
        acc1 += w1v[it] * sv;
    }
    #pragma unroll
    for (int o = 16; o > 0; o >>= 1) {
        acc0 += __shfl_down_sync(0xffffffffu, acc0, o);
        acc1 += __shfl_down_sync(0xffffffffu, acc1, o);
    }
    if (lane == 0) {
        g_pooled[b * E_ + e0 + 0] = acc0 * invD + v_b[e0 + 0];
        g_pooled[b * E_ + e0 + 1] = acc1 * invD + v_b[e0 + 1];
    }
}

// ============================================================
// Kernel 4: fused out-projection + residual (102.9us baseline).
// Reversed block order; plain img loads; .cs stores.
// Tail: re-zero g_a/g_qkb for the next graph replay.
// ============================================================
__global__ void __launch_bounds__(256) k_residual(const float* __restrict__ img,
                                                  const float* __restrict__ o_w,
                                                  const float* __restrict__ o_b,
                                                  float* __restrict__ out)
{
    int blk = (B_ * C_ - 1) - blockIdx.x;   // reversed: batch 31 first
    int b = blk / C_, c = blk - b * C_;
    int tid = threadIdx.x, lane = tid & 31;

    const float4* src = reinterpret_cast<const float4*>(img) + (size_t)blk * (N_ / 4);
    float4* dst = reinterpret_cast<float4*>(out) + (size_t)blk * (N_ / 4);

    // issue image loads first (784 float4: 3 per thread + 16-thread tail)
    float4 r0 = src[tid];
    float4 r1 = src[tid + 256];
    float4 r2 = src[tid + 512];
    float4 r3;
    if (tid < 16) r3 = src[tid + 768];

    // per-warp dot over e (o_w row + pooled row are cache-hot)
    const float* wr = o_w + (size_t)c * E_;
    const float* pl = g_pooled + b * E_;
    float p = 0.f;
    #pragma unroll
    for (int it = 0; it < 8; ++it) {
        int e = it * 32 + lane;
        p += wr[e] * pl[e];
    }
    #pragma unroll
    for (int o = 16; o > 0; o >>= 1) p += __shfl_xor_sync(0xffffffffu, p, o);
    float add = p + __ldg(&o_b[c]);

    // re-zero accumulators for the next replay (one element per block)
    if (tid == 64) {
        g_a[blk] = 0.f;
        if (blk < B_) g_qkb[blk] = 0.f;
    }

    r0.x += add; r0.y += add; r0.z += add; r0.w += add;
    r1.x += add; r1.y += add; r1.z += add; r1.w += add;
    r2.x += add; r2.y += add; r2.z += add; r2.w += add;
    __stcs(dst + tid, r0);
    __stcs(dst + tid + 256, r1);
    __stcs(dst + tid + 512, r2);
    if (tid < 16) {
        r3.x += add; r3.y += add; r3.z += add; r3.w += add;
        __stcs(dst + tid + 768, r3);
    }
}

// ============================================================
extern "C" void kernel_launch(void* const* d_in, const int* in_sizes, int n_in,
                              void* d_out, int out_size)
{
    const float* text = (const float*)d_in[0];
    const float* img  = (const float*)d_in[1];
    const float* q_w  = (const float*)d_in[2];
    const float* q_b  = (const float*)d_in[3];
    const float* k_w  = (const float*)d_in[4];
    const float* k_b  = (const float*)d_in[5];
    const float* v_w  = (const float*)d_in[6];
    const float* v_b  = (const float*)d_in[7];
    const float* o_w  = (const float*)d_in[8];
    const float* o_b  = (const float*)d_in[9];
    float* out = (float*)d_out;

    k_qa<<<dim3(32, B_), 256>>>(text, q_w, q_b, k_w, k_b);
    k_attn_pass<<<dim3(GX, B_), 256>>>(img);
    k_pool<<<dim3(B_, 16), 256>>>(v_w, v_b);
    k_residual<<<B_ * C_, 256>>>(img, o_w, o_b, out);
}